// round 1
// baseline (speedup 1.0000x reference)
#include <cuda_runtime.h>

#define BATCH 16384
#define DIM   1024
#define D4    256          // DIM/4 float4s per row
#define TT    128          // num degradation types
#define BM    64           // batch rows per block
#define NBLK  (BATCH/BM)   // 256 blocks
#define KB    32           // k-chunk
#define NCHUNK (DIM/KB)    // 32 chunks

__device__ float g_partials[NBLK];

__device__ __forceinline__ unsigned long long pack2(float a, float b) {
    unsigned long long r;
    asm("mov.b64 %0, {%1, %2};" : "=l"(r)
        : "r"(__float_as_uint(a)), "r"(__float_as_uint(b)));
    return r;
}
__device__ __forceinline__ unsigned long long dup2(float a) {
    unsigned long long r;
    asm("mov.b64 %0, {%1, %1};" : "=l"(r) : "r"(__float_as_uint(a)));
    return r;
}
// packed 2xFP32 FMA (sm_100+): d = a*b + d
__device__ __forceinline__ void fma2(unsigned long long& d,
                                     unsigned long long a,
                                     unsigned long long b) {
    asm("fma.rn.f32x2 %0, %1, %2, %0;" : "+l"(d) : "l"(a), "l"(b));
}
__device__ __forceinline__ float2 unpack2(unsigned long long v) {
    unsigned int lo, hi;
    asm("mov.b64 {%0, %1}, %2;" : "=r"(lo), "=r"(hi) : "l"(v));
    return make_float2(__uint_as_float(lo), __uint_as_float(hi));
}

__global__ __launch_bounds__(256, 2)
void qrl_fused_kernel(const float* __restrict__ X,      // [B, D]
                      const float* __restrict__ W,      // [T, D]
                      const float* __restrict__ bias,   // [T]
                      const int*   __restrict__ di,     // [B, 12]
                      const int*   __restrict__ dm)     // [B, 12]
{
    // GEMM tiles and logits buffer alias (logits live in regs during GEMM)
    __shared__ union SH {
        struct { float xs[KB][68]; float ws[KB][132]; } g;  // 25.0 KB
        float ls[BM][TT + 1];                               // 33.0 KB
    } sh;
    __shared__ float sbias[TT];
    __shared__ float sred[256];

    const int tid  = threadIdx.x;
    const int bid  = blockIdx.x;
    const int row0 = bid * BM;

    if (tid < TT) sbias[tid] = bias[tid];

    const float4* X4 = (const float4*)X;
    const float4* W4 = (const float4*)W;

    // ---- register-prefetched, smem-tiled GEMM: logits[64][128] ----
    float4 px[2], pw[4];
    {
        #pragma unroll
        for (int i = 0; i < 2; ++i) {
            int idx = tid + 256 * i, m = idx >> 3, c = idx & 7;
            px[i] = X4[(size_t)(row0 + m) * D4 + c];
        }
        #pragma unroll
        for (int i = 0; i < 4; ++i) {
            int idx = tid + 256 * i, t = idx >> 3, c = idx & 7;
            pw[i] = W4[(size_t)t * D4 + c];
        }
    }

    const int mi = tid & 15;   // m-tile: rows mi*4 .. mi*4+3
    const int ti = tid >> 4;   // t-tile: cols ti*8 .. ti*8+7
    unsigned long long acc[2][8];
    #pragma unroll
    for (int p = 0; p < 2; ++p)
        #pragma unroll
        for (int j = 0; j < 8; ++j) acc[p][j] = 0ULL;

    for (int kc = 0; kc < NCHUNK; ++kc) {
        __syncthreads();
        #pragma unroll
        for (int i = 0; i < 2; ++i) {
            int idx = tid + 256 * i, m = idx >> 3, c = idx & 7;
            sh.g.xs[4 * c + 0][m] = px[i].x;
            sh.g.xs[4 * c + 1][m] = px[i].y;
            sh.g.xs[4 * c + 2][m] = px[i].z;
            sh.g.xs[4 * c + 3][m] = px[i].w;
        }
        #pragma unroll
        for (int i = 0; i < 4; ++i) {
            int idx = tid + 256 * i, t = idx >> 3, c = idx & 7;
            sh.g.ws[4 * c + 0][t] = pw[i].x;
            sh.g.ws[4 * c + 1][t] = pw[i].y;
            sh.g.ws[4 * c + 2][t] = pw[i].z;
            sh.g.ws[4 * c + 3][t] = pw[i].w;
        }
        __syncthreads();

        if (kc + 1 < NCHUNK) {   // prefetch next chunk; latency hidden by compute
            int c0 = (kc + 1) * 8;
            #pragma unroll
            for (int i = 0; i < 2; ++i) {
                int idx = tid + 256 * i, m = idx >> 3, c = idx & 7;
                px[i] = X4[(size_t)(row0 + m) * D4 + c0 + c];
            }
            #pragma unroll
            for (int i = 0; i < 4; ++i) {
                int idx = tid + 256 * i, t = idx >> 3, c = idx & 7;
                pw[i] = W4[(size_t)t * D4 + c0 + c];
            }
        }

        #pragma unroll
        for (int k = 0; k < KB; ++k) {
            float4 xa = *(const float4*)&sh.g.xs[k][mi * 4];
            float4 wa = *(const float4*)&sh.g.ws[k][ti * 8];
            float4 wb = *(const float4*)&sh.g.ws[k][ti * 8 + 4];
            unsigned long long xp0 = pack2(xa.x, xa.y);
            unsigned long long xp1 = pack2(xa.z, xa.w);
            float wv[8] = {wa.x, wa.y, wa.z, wa.w, wb.x, wb.y, wb.z, wb.w};
            #pragma unroll
            for (int j = 0; j < 8; ++j) {
                unsigned long long wd = dup2(wv[j]);
                fma2(acc[0][j], xp0, wd);
                fma2(acc[1][j], xp1, wd);
            }
        }
    }

    // ---- logits (+bias) to shared ----
    __syncthreads();   // GEMM buffers dead; safe to alias with ls
    #pragma unroll
    for (int p = 0; p < 2; ++p)
        #pragma unroll
        for (int j = 0; j < 8; ++j) {
            float2 v = unpack2(acc[p][j]);
            int t = ti * 8 + j;
            int m = mi * 4 + p * 2;
            float bb = sbias[t];
            sh.ls[m][t]     = v.x + bb;
            sh.ls[m + 1][t] = v.y + bb;
        }
    __syncthreads();

    // ---- softmax + gather: 4 lanes cooperate per row ----
    const int r = tid >> 2;
    const int q = tid & 3;
    float mx = -3.0e38f;
    #pragma unroll
    for (int i = 0; i < 32; ++i) mx = fmaxf(mx, sh.ls[r][q + i * 4]);
    mx = fmaxf(mx, __shfl_xor_sync(0xffffffffu, mx, 1));
    mx = fmaxf(mx, __shfl_xor_sync(0xffffffffu, mx, 2));

    float se = 0.f;
    #pragma unroll
    for (int i = 0; i < 32; ++i) se += __expf(sh.ls[r][q + i * 4] - mx);
    se += __shfl_xor_sync(0xffffffffu, se, 1);
    se += __shfl_xor_sync(0xffffffffu, se, 2);

    float g = 0.f;
    const long base = (long)(row0 + r) * 12;
    #pragma unroll
    for (int j = q; j < 12; j += 4) {
        int idx = di[base + j];
        int msk = dm[base + j];
        if (msk) g += __expf(sh.ls[r][idx] - mx);
    }
    g += __shfl_xor_sync(0xffffffffu, g, 1);
    g += __shfl_xor_sync(0xffffffffu, g, 2);

    float part = (q == 0) ? (g / se) : 0.f;

    // deterministic block reduction
    sred[tid] = part;
    __syncthreads();
    #pragma unroll
    for (int s = 128; s > 0; s >>= 1) {
        if (tid < s) sred[tid] += sred[tid + s];
        __syncthreads();
    }
    if (tid == 0) g_partials[bid] = sred[0];
}

__global__ void qrl_finalize_kernel(float* __restrict__ out) {
    __shared__ float sred[NBLK];
    int tid = threadIdx.x;
    sred[tid] = g_partials[tid];
    __syncthreads();
    #pragma unroll
    for (int s = NBLK / 2; s > 0; s >>= 1) {
        if (tid < s) sred[tid] += sred[tid + s];
        __syncthreads();
    }
    if (tid == 0) out[0] = sred[0] * (1.0f / ((float)BATCH * 4.0f));  // /(B*V)
}

extern "C" void kernel_launch(void* const* d_in, const int* in_sizes, int n_in,
                              void* d_out, int out_size) {
    const float* X  = (const float*)d_in[0];   // clean_embeddings [B,D]
    const float* W  = (const float*)d_in[1];   // W [T,D]
    const float* b  = (const float*)d_in[2];   // b [T]
    const int*   di = (const int*)d_in[3];     // deg_indices [B,V,L]
    const int*   dm = (const int*)d_in[4];     // deg_mask    [B,V,L]

    qrl_fused_kernel<<<NBLK, 256>>>(X, W, b, di, dm);
    qrl_finalize_kernel<<<1, NBLK>>>((float*)d_out);
}

// round 3
// speedup vs baseline: 2.5798x; 2.5798x over previous
#include <cuda_runtime.h>
#include <cstdint>

#define BATCH 16384
#define DIM   1024
#define TT    128
#define BM    128                  // batch rows per CTA
#define NCTA  (BATCH/BM)           // 128
#define KC    32                   // K per chunk (32 f32 = 128B row)
#define NCHUNK (DIM/KC)            // 32
#define NSTAGE 3
#define A_BYTES 16384              // 128 rows x 128B
#define STAGE_BYTES 32768          // A + B
#define MISC_OFF (NSTAGE*STAGE_BYTES)      // 98304
#define SMEM_DYN (MISC_OFF + 1024)
#define LSTR 130                   // logits row stride (floats), even for float2

__device__ float g_partials[NCTA];
__device__ unsigned int g_done = 0;   // self-resets via atomicInc wrap

// ---------------- PTX helpers ----------------
__device__ __forceinline__ uint32_t smem_u32(const void* p) {
    uint32_t a;
    asm("{ .reg .u64 t; cvta.to.shared.u64 t, %1; cvt.u32.u64 %0, t; }"
        : "=r"(a) : "l"(p));
    return a;
}
__device__ __forceinline__ void cp_async16(uint32_t saddr, const void* gaddr) {
    asm volatile("cp.async.cg.shared.global [%0], [%1], 16;"
                 :: "r"(saddr), "l"(gaddr) : "memory");
}
__device__ __forceinline__ uint32_t swz(uint32_t off) {   // SW128
    return off ^ ((off >> 3) & 0x70);
}
__device__ __forceinline__ uint32_t f2tf32(float x) {
    uint32_t r;
    asm("cvt.rna.tf32.f32 %0, %1;" : "=r"(r) : "f"(x));
    return r;
}
template <int IMM>
__device__ __forceinline__ float lds_imm(uint32_t base) {
    float v;
    asm volatile("ld.shared.f32 %0, [%1+%2];" : "=f"(v) : "r"(base), "n"(IMM));
    return v;
}
__device__ __forceinline__ void mma_tf32(float d[4],
                                         uint32_t a0, uint32_t a1, uint32_t a2, uint32_t a3,
                                         uint32_t b0, uint32_t b1) {
    asm volatile(
        "mma.sync.aligned.m16n8k8.row.col.f32.tf32.tf32.f32 "
        "{%0,%1,%2,%3}, {%4,%5,%6,%7}, {%8,%9}, {%0,%1,%2,%3};"
        : "+f"(d[0]), "+f"(d[1]), "+f"(d[2]), "+f"(d[3])
        : "r"(a0), "r"(a1), "r"(a2), "r"(a3), "r"(b0), "r"(b1));
}

// ---------------- fused kernel ----------------
__global__ __launch_bounds__(256, 1)
void qrl_mma_kernel(const float* __restrict__ X,     // [B, D]
                    const float* __restrict__ W,     // [T, D]
                    const float* __restrict__ bias,  // [T]
                    const int*   __restrict__ di,    // [B, 12]
                    const int*   __restrict__ dm,    // [B, 12]
                    float* __restrict__ out)
{
    extern __shared__ __align__(128) char smem[];
    float* ls    = (float*)smem;                     // aliases stage buffers post-GEMM
    float* sbias = (float*)(smem + MISC_OFF);        // 128 floats
    float* sred  = (float*)(smem + MISC_OFF + 512);  // 8 floats
    int*   sflag = (int*)  (smem + MISC_OFF + 576);

    const uint32_t sbase = smem_u32(smem);
    const int tid  = threadIdx.x;
    const int wid  = tid >> 5;
    const int lane = tid & 31;
    const int bid  = blockIdx.x;
    const int row0 = bid * BM;

    const int wm = wid & 3;        // 4 warps in M: 32 rows each
    const int wn = wid >> 2;       // 2 warps in N: 64 cols each
    const int g  = lane >> 2;      // 0..7
    const int c  = lane & 3;       // 0..3
    const uint32_t xr = (uint32_t)(g * 16);    // swizzle XOR term (row&7 == g for all frag rows)
    const uint32_t c4 = (uint32_t)(c * 4);
    const uint32_t arow = (uint32_t)((wm * 32 + g) * 128);
    const uint32_t brow = (uint32_t)((wn * 64 + g) * 128);

    if (tid < TT) sbias[tid] = bias[tid];

    // ---- cp.async chunk loader (A = X tile, B = W chunk, SW128-swizzled) ----
    auto load_chunk = [&](int kc, int st) {
        const uint32_t sa = sbase + st * STAGE_BYTES;
        #pragma unroll
        for (int i = 0; i < 4; ++i) {
            int idx = tid + 256 * i;               // 0..1023
            int r = idx >> 3, seg = idx & 7;
            uint32_t so = swz((uint32_t)(r * 128 + seg * 16));
            cp_async16(sa + so,           X + (size_t)(row0 + r) * DIM + kc * KC + seg * 4);
            cp_async16(sa + A_BYTES + so, W + (size_t)r * DIM + kc * KC + seg * 4);
        }
        asm volatile("cp.async.commit_group;" ::: "memory");
    };

    float acc[2][8][4];
    #pragma unroll
    for (int i = 0; i < 2; ++i)
        #pragma unroll
        for (int j = 0; j < 8; ++j)
            #pragma unroll
            for (int q = 0; q < 4; ++q) acc[i][j][q] = 0.f;

    load_chunk(0, 0);
    load_chunk(1, 1);

    for (int kc = 0; kc < NCHUNK; ++kc) {
        const int st = kc % NSTAGE;
        if (kc < NCHUNK - 2) asm volatile("cp.async.wait_group 1;" ::: "memory");
        else                 asm volatile("cp.async.wait_group 0;" ::: "memory");
        __syncthreads();
        if (kc + 2 < NCHUNK) load_chunk(kc + 2, (kc + 2) % NSTAGE);

        const uint32_t abase = sbase + st * STAGE_BYTES;
        const uint32_t bbase = abase + A_BYTES;

        #pragma unroll
        for (int ks = 0; ks < 4; ++ks) {
            const uint32_t o0 = ((uint32_t)(ks * 32) + c4) ^ xr;   // (k0+c)*4 ^ xr
            const uint32_t o1 = o0 ^ 16u;                          // (k0+c+4)*4 ^ xr
            const uint32_t rA0 = abase + arow + o0;
            const uint32_t rA1 = abase + arow + o1;
            const uint32_t rB0 = bbase + brow + o0;
            const uint32_t rB1 = bbase + brow + o1;

            // A fragments: 2 m-tiles x {a0,a1,a2,a3}
            uint32_t a[2][4];
            a[0][0] = f2tf32(lds_imm<0>(rA0));
            a[0][1] = f2tf32(lds_imm<1024>(rA0));    // +8 rows
            a[0][2] = f2tf32(lds_imm<0>(rA1));
            a[0][3] = f2tf32(lds_imm<1024>(rA1));
            a[1][0] = f2tf32(lds_imm<2048>(rA0));    // +16 rows
            a[1][1] = f2tf32(lds_imm<3072>(rA0));
            a[1][2] = f2tf32(lds_imm<2048>(rA1));
            a[1][3] = f2tf32(lds_imm<3072>(rA1));

            // B fragments: 8 n-tiles x {b0,b1}
            uint32_t b[8][2];
            b[0][0] = f2tf32(lds_imm<0>(rB0));      b[0][1] = f2tf32(lds_imm<0>(rB1));
            b[1][0] = f2tf32(lds_imm<1024>(rB0));   b[1][1] = f2tf32(lds_imm<1024>(rB1));
            b[2][0] = f2tf32(lds_imm<2048>(rB0));   b[2][1] = f2tf32(lds_imm<2048>(rB1));
            b[3][0] = f2tf32(lds_imm<3072>(rB0));   b[3][1] = f2tf32(lds_imm<3072>(rB1));
            b[4][0] = f2tf32(lds_imm<4096>(rB0));   b[4][1] = f2tf32(lds_imm<4096>(rB1));
            b[5][0] = f2tf32(lds_imm<5120>(rB0));   b[5][1] = f2tf32(lds_imm<5120>(rB1));
            b[6][0] = f2tf32(lds_imm<6144>(rB0));   b[6][1] = f2tf32(lds_imm<6144>(rB1));
            b[7][0] = f2tf32(lds_imm<7168>(rB0));   b[7][1] = f2tf32(lds_imm<7168>(rB1));

            #pragma unroll
            for (int i = 0; i < 2; ++i)
                #pragma unroll
                for (int j = 0; j < 8; ++j)
                    mma_tf32(acc[i][j], a[i][0], a[i][1], a[i][2], a[i][3],
                             b[j][0], b[j][1]);
        }
    }

    // ---- write logits to smem (alias stage buffers) ----
    __syncthreads();
    #pragma unroll
    for (int i = 0; i < 2; ++i) {
        const int r0 = wm * 32 + i * 16 + g;
        #pragma unroll
        for (int j = 0; j < 8; ++j) {
            const int c0 = wn * 64 + j * 8 + 2 * c;
            *(float2*)&ls[(size_t)r0 * LSTR + c0]       = make_float2(acc[i][j][0], acc[i][j][1]);
            *(float2*)&ls[(size_t)(r0 + 8) * LSTR + c0] = make_float2(acc[i][j][2], acc[i][j][3]);
        }
    }
    __syncthreads();

    // ---- softmax + gather: 2 lanes per row ----
    const int r = tid >> 1;
    const int h = tid & 1;
    const float* lr = &ls[(size_t)r * LSTR];

    float mx = -3.0e38f;
    #pragma unroll
    for (int i = 0; i < 64; ++i) {
        int cc = h + 2 * i;
        mx = fmaxf(mx, lr[cc] + sbias[cc]);
    }
    mx = fmaxf(mx, __shfl_xor_sync(0xffffffffu, mx, 1));

    float se = 0.f;
    #pragma unroll
    for (int i = 0; i < 64; ++i) {
        int cc = h + 2 * i;
        se += __expf(lr[cc] + sbias[cc] - mx);
    }
    se += __shfl_xor_sync(0xffffffffu, se, 1);

    float gg = 0.f;
    const int* dip = di + (size_t)(row0 + r) * 12;
    const int* dmp = dm + (size_t)(row0 + r) * 12;
    #pragma unroll
    for (int j = 0; j < 12; ++j) {
        if ((j & 1) == h) {
            int idx = dip[j];
            if (dmp[j]) gg += __expf(lr[idx] + sbias[idx] - mx);
        }
    }
    gg += __shfl_xor_sync(0xffffffffu, gg, 1);

    float part = (h == 0) ? (gg / se) : 0.f;

    // deterministic block reduce (8 warps)
    #pragma unroll
    for (int o = 16; o; o >>= 1) part += __shfl_down_sync(0xffffffffu, part, o);
    if (lane == 0) sred[wid] = part;
    __syncthreads();
    if (tid == 0) {
        float s = ((sred[0] + sred[1]) + (sred[2] + sred[3]))
                + ((sred[4] + sred[5]) + (sred[6] + sred[7]));
        g_partials[bid] = s;
        __threadfence();
        unsigned old = atomicInc(&g_done, NCTA - 1);   // wraps to 0: replay-safe
        sflag[0] = (old == NCTA - 1) ? 1 : 0;
    }
    __syncthreads();

    // ---- fused finalize: last CTA reduces all partials ----
    if (sflag[0]) {
        __threadfence();
        float v = (tid < NCTA) ? g_partials[tid] : 0.f;
        #pragma unroll
        for (int o = 16; o; o >>= 1) v += __shfl_down_sync(0xffffffffu, v, o);
        if (lane == 0) sred[wid] = v;
        __syncthreads();
        if (tid == 0) {
            float s = ((sred[0] + sred[1]) + (sred[2] + sred[3]))
                    + ((sred[4] + sred[5]) + (sred[6] + sred[7]));
            out[0] = s * (1.0f / 65536.f);   // / (B * V)
        }
    }
}

extern "C" void kernel_launch(void* const* d_in, const int* in_sizes, int n_in,
                              void* d_out, int out_size) {
    const float* X  = (const float*)d_in[0];
    const float* W  = (const float*)d_in[1];
    const float* b  = (const float*)d_in[2];
    const int*   di = (const int*)d_in[3];
    const int*   dm = (const int*)d_in[4];

    cudaFuncSetAttribute(qrl_mma_kernel,
                         cudaFuncAttributeMaxDynamicSharedMemorySize, SMEM_DYN);
    qrl_mma_kernel<<<NCTA, 256, SMEM_DYN>>>(X, W, b, di, dm, (float*)d_out);
}